// round 12
// baseline (speedup 1.0000x reference)
#include <cuda_runtime.h>
#include <cuda_bf16.h>

// Problem constants (fixed by the dataset):
//   acts: (B, T, U+1, V) fp32, labels: (B, U) int32, act_lens/label_lens: (B,) int32
#define BB  16
#define TT  200
#define UU  100
#define VV  256
#define UP1 101          // U + 1
#define NEG_INF (-1e30f)

// Guarded smem tiles: row t index range [-1, TT] -> TT+2 rows.
#define NBG ((TT + 2) * UP1)    // 20402 floats
#define NEG ((TT + 2) * UU)     // 20200 floats

// Scratch (no cudaMalloc allowed).
__device__ float    g_blank[BB * TT * UP1];   // (B, T, U+1)
__device__ float    g_emit [BB * TT * UU];    // (B, T, U)
__device__ float    g_perb [BB];              // per-example nll / label_len
__device__ unsigned g_done = 0;               // block-completion counter

// ---------------------------------------------------------------------------
// Kernel 1: fused log-softmax gather, TWO (b,t,u) nodes per warp (MLP=4).
// Skips nodes outside the live lattice region. (Measured at effective-BW
// roofline in earlier rounds; 4-node variant regressed on register pressure.)
// ---------------------------------------------------------------------------
__global__ __launch_bounds__(256) void rnnt_softmax_kernel(
    const float* __restrict__ acts,
    const int*   __restrict__ labels,
    const int*   __restrict__ act_lens,
    const int*   __restrict__ label_lens)
{
    const int P = BB * TT * UP1;                       // 323200 (even)
    int w    = blockIdx.x * 8 + (threadIdx.x >> 5);    // warp id
    int lane = threadIdx.x & 31;
    int n0   = w * 2;
    if (n0 >= P) return;
    int n1 = n0 + 1;

    int u0 = n0 % UP1, bt0 = n0 / UP1, t0 = bt0 % TT, b0i = bt0 / TT;
    int u1 = n1 % UP1, bt1 = n1 / UP1, t1 = bt1 % TT, b1i = bt1 / TT;

    bool L0 = (t0 < __ldg(act_lens + b0i)) && (u0 <= __ldg(label_lens + b0i));
    bool L1 = (t1 < __ldg(act_lens + b1i)) && (u1 <= __ldg(label_lens + b1i));
    if (!L0 && !L1) return;

    const float4* p0 = reinterpret_cast<const float4*>(acts) + (size_t)n0 * (VV / 4);
    const float4* p1 = p0 + (VV / 4);

    float4 a0 = {0,0,0,0}, c0 = {0,0,0,0}, a1 = {0,0,0,0}, c1 = {0,0,0,0};
    if (L0) { a0 = p0[lane]; c0 = p0[lane + 32]; }
    if (L1) { a1 = p1[lane]; c1 = p1[lane + 32]; }

    float m0 = fmaxf(fmaxf(fmaxf(a0.x, a0.y), fmaxf(a0.z, a0.w)),
                     fmaxf(fmaxf(c0.x, c0.y), fmaxf(c0.z, c0.w)));
    float m1 = fmaxf(fmaxf(fmaxf(a1.x, a1.y), fmaxf(a1.z, a1.w)),
                     fmaxf(fmaxf(c1.x, c1.y), fmaxf(c1.z, c1.w)));
    #pragma unroll
    for (int o = 16; o; o >>= 1) {
        m0 = fmaxf(m0, __shfl_xor_sync(0xffffffffu, m0, o));
        m1 = fmaxf(m1, __shfl_xor_sync(0xffffffffu, m1, o));
    }

    float s0 = __expf(a0.x - m0) + __expf(a0.y - m0) + __expf(a0.z - m0) + __expf(a0.w - m0)
             + __expf(c0.x - m0) + __expf(c0.y - m0) + __expf(c0.z - m0) + __expf(c0.w - m0);
    float s1 = __expf(a1.x - m1) + __expf(a1.y - m1) + __expf(a1.z - m1) + __expf(a1.w - m1)
             + __expf(c1.x - m1) + __expf(c1.y - m1) + __expf(c1.z - m1) + __expf(c1.w - m1);
    #pragma unroll
    for (int o = 16; o; o >>= 1) {
        s0 += __shfl_xor_sync(0xffffffffu, s0, o);
        s1 += __shfl_xor_sync(0xffffffffu, s1, o);
    }

    if (lane == 0) {
        if (L0) {
            float logZ = m0 + __logf(s0);
            g_blank[n0] = a0.x - logZ;                 // a0.x on lane0 = blank logit
            if (u0 < UU) {
                int lbl  = labels[b0i * UU + u0];
                float lv = __ldg(acts + (size_t)n0 * VV + lbl);
                g_emit[bt0 * UU + u0] = lv - logZ;
            }
        }
        if (L1) {
            float logZ = m1 + __logf(s1);
            g_blank[n1] = a1.x - logZ;
            if (u1 < UU) {
                int lbl  = labels[b1i * UU + u1];
                float lv = __ldg(acts + (size_t)n1 * VV + lbl);
                g_emit[bt1 * UU + u1] = lv - logZ;
            }
        }
    }
}

// ---------------------------------------------------------------------------
// Kernel 2: per-example forward DP over 4 warps (u = 32*warp + lane), with a
// RADIX-2 diagonal step: each phase advances TWO diagonals.
//   alpha[D+2][u] = LA3( alpha[D][u]   + W0,
//                        alpha[D][u-1] + W1,
//                        alpha[D][u-2] + W2 )
// where W0/W1/W2 are path weights computed from the (static) blank/emit tiles
// OFF the serial chain. Validity masks are replaced by NEG_INF guard rows
// (t = -1 and t in [Tl, TT]) baked into the staged smem tiles: invalid cells
// decay toward -inf and never feed valid cells (deps flow up in u, fwd in t).
// Cross-warp boundary: lanes 30/31 publish per phase, double-buffered + BAR.
// ---------------------------------------------------------------------------
__global__ __launch_bounds__(128) void rnnt_dp_kernel(
    const int* __restrict__ act_lens,
    const int* __restrict__ label_lens,
    float*     __restrict__ out)
{
    int b   = blockIdx.x;
    int Tl  = act_lens[b];
    int Ul  = label_lens[b];
    int tid = threadIdx.x;
    int w   = tid >> 5;
    int l   = tid & 31;

    extern __shared__ float sm[];
    float* sb = sm;            // (TT+2) * UP1, row index = t+1
    float* se = sm + NBG;      // (TT+2) * UU,  row index = t+1
    __shared__ float2 bd[2][4];  // [parity][warp] = {alpha[D][32w+30], alpha[D][32w+31]}

    // Pass 1: fill everything with NEG_INF (guards included).
    {
        const int TOT4 = (NBG + NEG) / 4;          // 10150 float4 (2 scalars left)
        float4 nf = make_float4(NEG_INF, NEG_INF, NEG_INF, NEG_INF);
        float4* s4 = reinterpret_cast<float4*>(sm);
        for (int i = tid; i < TOT4; i += 128) s4[i] = nf;
        if (tid < (NBG + NEG) - TOT4 * 4) sm[TOT4 * 4 + tid] = NEG_INF;
        if (tid < 8) bd[tid >> 2][tid & 3] = make_float2(NEG_INF, NEG_INF);
    }
    __syncthreads();

    // Pass 2: copy the live rows (t in [0, Tl)) on top of the guard fill.
    {
        const float*  gb  = g_blank + (size_t)b * TT * UP1;
        const float*  ge  = g_emit  + (size_t)b * TT * UU;
        const float4* gb4 = reinterpret_cast<const float4*>(gb);
        const float4* ge4 = reinterpret_cast<const float4*>(ge);
        int nbv = Tl * UP1;
        int nev = Tl * UU;                          // divisible by 4
        for (int i4 = tid; i4 < nbv / 4; i4 += 128) {
            float4 v = gb4[i4];
            int i = i4 * 4;
            sb[UP1 + i]     = v.x; sb[UP1 + i + 1] = v.y;
            sb[UP1 + i + 2] = v.z; sb[UP1 + i + 3] = v.w;
        }
        for (int i = (nbv / 4) * 4 + tid; i < nbv; i += 128) sb[UP1 + i] = gb[i];
        for (int i4 = tid; i4 < nev / 4; i4 += 128) {
            float4 v = ge4[i4];
            int i = i4 * 4;
            se[UU + i]     = v.x; se[UU + i + 1] = v.y;
            se[UU + i + 2] = v.z; se[UU + i + 3] = v.w;
        }
    }
    __syncthreads();

    const unsigned F = 0xffffffffu;
    int u   = w * 32 + l;                     // fixed u per lane (0..127)
    int uc  = min(u, UU);                     // sb column u
    int ucm = min(max(u - 1, 0), UU);         // sb column u-1
    int ue  = min(max(u - 1, 0), UU - 1);     // se column u-1
    int ue2 = min(max(u - 2, 0), UU - 1);     // se column u-2
    // (column clamps only trigger where the alpha operand is NEG_INF anyway)

    float pp = (u == 0) ? 0.0f : NEG_INF;     // alpha[0][u]
    int dmax = (Tl - 1) + Ul;
    int D = 0, par = 0;

    while (D + 2 <= dmax) {
        float2 nb = (w > 0) ? bd[par][w - 1] : make_float2(NEG_INF, NEG_INF);

        // Path weights for alpha[D] -> alpha[D+2] (off the serial chain).
        int tau = D + 1 - u;
        int im1 = min(max(tau - 1, -1), TT) + 1;
        int i0  = min(max(tau,     -1), TT) + 1;
        int ip1 = min(max(tau + 1, -1), TT) + 1;
        float b_m1u   = sb[im1 * UP1 + uc];
        float b_0u    = sb[i0  * UP1 + uc];
        float b_0um1  = sb[i0  * UP1 + ucm];
        float e_0um1  = se[i0  * UU + ue];
        float e_p1um1 = se[ip1 * UU + ue];
        float e_p1um2 = se[ip1 * UU + ue2];

        float W0 = b_m1u + b_0u;                       // blank, blank
        float A  = e_0um1 + b_0u;                      // emit then blank
        float Bp = b_0um1 + e_p1um1;                   // blank then emit
        float ma = fmaxf(A, Bp), na = fminf(A, Bp);
        float W1 = ma + __logf(1.0f + __expf(na - ma));
        float W2 = e_p1um2 + e_p1um1;                  // emit, emit

        // Serial chain: 2 shfls + 3-way logaddexp.
        float s1 = __shfl_up_sync(F, pp, 1);
        float s2 = __shfl_up_sync(F, pp, 2);
        if (l == 0)      { s1 = nb.y; s2 = nb.x; }
        else if (l == 1) { s2 = nb.y; }

        float x0 = pp + W0;
        float x1 = s1 + W1;
        float x2 = s2 + W2;
        float m  = fmaxf(fmaxf(x0, x1), x2);
        float sm3 = __expf(x0 - m) + __expf(x1 - m) + __expf(x2 - m);
        pp = m + __logf(sm3);

        if (l >= 30 && w < 3)
            reinterpret_cast<float*>(&bd[par ^ 1][w])[l - 30] = pp;
        par ^= 1;
        D += 2;
        __syncthreads();
    }

    if (D < dmax) {                            // single leftover diagonal
        float2 nb = (w > 0) ? bd[par][w - 1] : make_float2(NEG_INF, NEG_INF);
        int t   = (D + 1) - u;
        int itb = min(max(t - 1, -1), TT) + 1;
        int ite = min(max(t,     -1), TT) + 1;
        float bv = sb[itb * UP1 + uc];
        float ev = se[ite * UU  + ue];
        float lf = __shfl_up_sync(F, pp, 1);
        if (l == 0) lf = nb.y;
        float fb = pp + bv, fl = lf + ev;
        float mx = fmaxf(fb, fl), mn = fminf(fb, fl);
        pp = mx + __logf(1.0f + __expf(mn - mx));
    }

    // Terminal cell: lane with u == Ul holds alpha(Tl-1, Ul).
    if (u == Ul) {
        g_perb[b] = -(pp + sb[Tl * UP1 + Ul]) / (float)Ul;   // row Tl = t (Tl-1)+1
        __threadfence();
        unsigned done = atomicAdd(&g_done, 1u);
        if (done == BB - 1) {                 // last example: fold the mean
            __threadfence();
            float s = 0.0f;
            #pragma unroll
            for (int i = 0; i < BB; ++i) s += __ldcg(&g_perb[i]);
            out[0] = s / (float)BB;
            g_done = 0;                       // reset for next graph replay
        }
    }
}

extern "C" void kernel_launch(void* const* d_in, const int* in_sizes, int n_in,
                              void* d_out, int out_size)
{
    const float* acts       = (const float*)d_in[0];
    const int*   labels     = (const int*)  d_in[1];
    const int*   act_lens   = (const int*)  d_in[2];
    const int*   label_lens = (const int*)  d_in[3];
    float*       out        = (float*)d_out;

    const int P     = BB * TT * UP1;          // lattice nodes
    const int pairs = P / 2;                  // two nodes per warp
    int blocks = (pairs + 7) / 8;             // 8 warps per 256-thread block
    rnnt_softmax_kernel<<<blocks, 256>>>(acts, labels, act_lens, label_lens);

    size_t smem = (size_t)(NBG + NEG) * sizeof(float);   // 162,408 B dynamic
    cudaFuncSetAttribute(rnnt_dp_kernel,
                         cudaFuncAttributeMaxDynamicSharedMemorySize, (int)smem);
    rnnt_dp_kernel<<<BB, 128, smem>>>(act_lens, label_lens, out);
}